// round 1
// baseline (speedup 1.0000x reference)
#include <cuda_runtime.h>
#include <math.h>

// Problem constants
#define TT   2048      // tokens
#define CC   1024      // in_features
#define HH   4096      // hidden_features
#define NE   8         // experts
#define NG   16        // gate dim
#define RCAP 3072      // padded row capacity (worst case: 7*128 + 2048 = 2944)
#define EPSN 1e-4f

// ---------------- device scratch (static: allocation-free) ----------------
__device__ float g_unit[NE * NG];            // unit-normalized gate vectors
__device__ int   g_idx[TT];                  // selected expert per token
__device__ float g_score[TT];                // max softmax per token
__device__ int   g_counts[NE];
__device__ int   g_off[NE + 1];              // 128-aligned segment offsets
__device__ int   g_fill[NE];
__device__ int   g_perm[RCAP];               // padded row -> token (-1 = pad)
__device__ float g_Xg[(size_t)RCAP * CC];    // gathered inputs (12 MB)
__device__ float g_H[(size_t)RCAP * HH];     // hidden activations (48 MB)

// ---------------- kernel 0: normalize gate vectors, zero counters ----------
__global__ void prep_kernel(const float* __restrict__ wg) {
    int tid = threadIdx.x;
    if (tid < NE) {
        float s = 0.f;
        #pragma unroll
        for (int g = 0; g < NG; g++) { float v = wg[tid * NG + g]; s += v * v; }
        float nrm = fmaxf(sqrtf(s), EPSN);
        #pragma unroll
        for (int g = 0; g < NG; g++) g_unit[tid * NG + g] = wg[tid * NG + g] / nrm;
        g_counts[tid] = 0;
        g_fill[tid]   = 0;
    }
}

// ---------------- kernel 1: gating (warp per token) -----------------------
__global__ void gate_kernel(const float* __restrict__ x,
                            const float* __restrict__ wgred) {
    int warp = threadIdx.x >> 5;
    int lane = threadIdx.x & 31;
    int t = blockIdx.x * 8 + warp;
    const float* xr = x + (size_t)t * CC;

    // stage 1: xr16 = x . wg_red^T  (16 dots of length 1024)
    float acc[NG];
    #pragma unroll
    for (int g = 0; g < NG; g++) acc[g] = 0.f;
    for (int c = lane; c < CC; c += 32) {
        float xv = xr[c];
        #pragma unroll
        for (int g = 0; g < NG; g++) acc[g] += xv * wgred[g * CC + c];
    }
    #pragma unroll
    for (int g = 0; g < NG; g++) {
        #pragma unroll
        for (int o = 16; o > 0; o >>= 1)
            acc[g] += __shfl_xor_sync(0xFFFFFFFFu, acc[g], o);
    }

    // stage 2: logits = xr16 . unit^T, one expert per lane 0..7
    float logit = -1e30f;
    if (lane < NE) {
        float s = 0.f;
        #pragma unroll
        for (int g = 0; g < NG; g++) s += acc[g] * g_unit[lane * NG + g];
        logit = s;
    }
    // reductions restricted to xor offsets 4,2,1: lanes 0..7 stay in-group
    float m = logit;
    #pragma unroll
    for (int o = 4; o > 0; o >>= 1) m = fmaxf(m, __shfl_xor_sync(0xFFFFFFFFu, m, o));
    int idxm = (lane < NE && logit == m) ? lane : NE;   // first max index
    #pragma unroll
    for (int o = 4; o > 0; o >>= 1) idxm = min(idxm, __shfl_xor_sync(0xFFFFFFFFu, idxm, o));
    float ssum = (lane < NE) ? expf(logit - m) : 0.f;
    #pragma unroll
    for (int o = 4; o > 0; o >>= 1) ssum += __shfl_xor_sync(0xFFFFFFFFu, ssum, o);

    if (lane == 0) {
        g_idx[t]   = idxm;
        g_score[t] = 1.f / ssum;          // exp(lmax-lmax)/sum = max softmax
        atomicAdd(&g_counts[idxm], 1);
    }
}

// ---------------- kernel 2: 128-aligned segment offsets --------------------
__global__ void offs_kernel() {
    if (threadIdx.x == 0 && blockIdx.x == 0) {
        int o = 0;
        for (int e = 0; e < NE; e++) {
            g_off[e] = o;
            o += (g_counts[e] + 127) & ~127;
        }
        g_off[NE] = o;
    }
}

// ---------------- kernel 3/4: perm init + scatter ---------------------------
__global__ void initperm_kernel() {
    int i = blockIdx.x * blockDim.x + threadIdx.x;
    if (i < RCAP) g_perm[i] = -1;
}
__global__ void scatter_kernel() {
    int t = blockIdx.x * blockDim.x + threadIdx.x;
    if (t < TT) {
        int e = g_idx[t];
        int p = g_off[e] + atomicAdd(&g_fill[e], 1);
        g_perm[p] = t;
    }
}

// ---------------- kernel 5: gather x rows into expert-sorted layout --------
__global__ void gather_kernel(const float* __restrict__ x) {
    int r = blockIdx.x;
    int t = g_perm[r];
    float4* dst = (float4*)(g_Xg + (size_t)r * CC);
    if (t >= 0) {
        const float4* src = (const float4*)(x + (size_t)t * CC);
        dst[threadIdx.x] = src[threadIdx.x];    // 256 thr * float4 = 1024 floats
    } else {
        dst[threadIdx.x] = make_float4(0.f, 0.f, 0.f, 0.f);
    }
}

// ---------------- GEMM 1: H = gelu(Xg @ w1[e] + b1[e]) ---------------------
// 128x128 C-tile, BK=16, 256 threads, 8x8 per thread.
__global__ __launch_bounds__(256, 2)
void gemm1_kernel(const float* __restrict__ w1, const float* __restrict__ b1) {
    const int BM = 128, BN = 128, BK = 16;
    __shared__ float As[BK][BM];
    __shared__ float Bs[BK][BN];

    int m0 = blockIdx.y * BM;
    int n0 = blockIdx.x * BN;
    if (m0 >= g_off[NE]) return;
    int e = 0;
    #pragma unroll
    for (int i = 1; i < NE; i++) if (m0 >= g_off[i]) e = i;
    if (m0 >= g_off[e] + g_counts[e]) return;   // pure-pad tile

    const float* A = g_Xg + (size_t)m0 * CC;
    const float* B = w1 + (size_t)e * CC * HH + n0;

    int tid = threadIdx.x;
    int tx = tid & 15, ty = tid >> 4;
    float acc[8][8];
    #pragma unroll
    for (int i = 0; i < 8; i++)
        #pragma unroll
        for (int j = 0; j < 8; j++) acc[i][j] = 0.f;

    for (int k0 = 0; k0 < CC; k0 += BK) {
        #pragma unroll
        for (int i = 0; i < 2; i++) {           // A tile 128x16, transposed store
            int idx = tid + i * 256;
            int r = idx >> 2, c4 = (idx & 3) * 4;
            float4 v = *(const float4*)(A + (size_t)r * CC + k0 + c4);
            As[c4 + 0][r] = v.x; As[c4 + 1][r] = v.y;
            As[c4 + 2][r] = v.z; As[c4 + 3][r] = v.w;
        }
        #pragma unroll
        for (int i = 0; i < 2; i++) {           // B tile 16x128
            int idx = tid + i * 256;
            int r = idx >> 5, c = (idx & 31) * 4;
            *(float4*)(&Bs[r][c]) = *(const float4*)(B + (size_t)(k0 + r) * HH + c);
        }
        __syncthreads();
        #pragma unroll
        for (int kk = 0; kk < BK; kk++) {
            float a[8], b[8];
            *(float4*)(a)     = *(const float4*)(&As[kk][ty * 8]);
            *(float4*)(a + 4) = *(const float4*)(&As[kk][ty * 8 + 4]);
            *(float4*)(b)     = *(const float4*)(&Bs[kk][tx * 8]);
            *(float4*)(b + 4) = *(const float4*)(&Bs[kk][tx * 8 + 4]);
            #pragma unroll
            for (int i = 0; i < 8; i++)
                #pragma unroll
                for (int j = 0; j < 8; j++) acc[i][j] += a[i] * b[j];
        }
        __syncthreads();
    }

    #pragma unroll
    for (int i = 0; i < 8; i++) {
        int row = m0 + ty * 8 + i;
        float* Hrow = g_H + (size_t)row * HH + n0 + tx * 8;
        #pragma unroll
        for (int j = 0; j < 8; j++) {
            float v = acc[i][j] + b1[(size_t)e * HH + n0 + tx * 8 + j];
            acc[i][j] = 0.5f * v * (1.0f + erff(v * 0.70710678118654752f)); // exact gelu
        }
        *(float4*)(Hrow)     = *(float4*)(&acc[i][0]);
        *(float4*)(Hrow + 4) = *(float4*)(&acc[i][4]);
    }
}

// ---------------- GEMM 2: out[token] = (H @ w2[e] + b2[e]) * score ---------
__global__ __launch_bounds__(256, 2)
void gemm2_kernel(const float* __restrict__ w2, const float* __restrict__ b2,
                  float* __restrict__ out) {
    const int BM = 128, BN = 128, BK = 16;
    __shared__ float As[BK][BM];
    __shared__ float Bs[BK][BN];

    int m0 = blockIdx.y * BM;
    int n0 = blockIdx.x * BN;
    if (m0 >= g_off[NE]) return;
    int e = 0;
    #pragma unroll
    for (int i = 1; i < NE; i++) if (m0 >= g_off[i]) e = i;
    if (m0 >= g_off[e] + g_counts[e]) return;

    const float* A = g_H + (size_t)m0 * HH;
    const float* B = w2 + (size_t)e * HH * CC + n0;

    int tid = threadIdx.x;
    int tx = tid & 15, ty = tid >> 4;
    float acc[8][8];
    #pragma unroll
    for (int i = 0; i < 8; i++)
        #pragma unroll
        for (int j = 0; j < 8; j++) acc[i][j] = 0.f;

    for (int k0 = 0; k0 < HH; k0 += BK) {
        #pragma unroll
        for (int i = 0; i < 2; i++) {
            int idx = tid + i * 256;
            int r = idx >> 2, c4 = (idx & 3) * 4;
            float4 v = *(const float4*)(A + (size_t)r * HH + k0 + c4);
            As[c4 + 0][r] = v.x; As[c4 + 1][r] = v.y;
            As[c4 + 2][r] = v.z; As[c4 + 3][r] = v.w;
        }
        #pragma unroll
        for (int i = 0; i < 2; i++) {
            int idx = tid + i * 256;
            int r = idx >> 5, c = (idx & 31) * 4;
            *(float4*)(&Bs[r][c]) = *(const float4*)(B + (size_t)(k0 + r) * CC + c);
        }
        __syncthreads();
        #pragma unroll
        for (int kk = 0; kk < BK; kk++) {
            float a[8], b[8];
            *(float4*)(a)     = *(const float4*)(&As[kk][ty * 8]);
            *(float4*)(a + 4) = *(const float4*)(&As[kk][ty * 8 + 4]);
            *(float4*)(b)     = *(const float4*)(&Bs[kk][tx * 8]);
            *(float4*)(b + 4) = *(const float4*)(&Bs[kk][tx * 8 + 4]);
            #pragma unroll
            for (int i = 0; i < 8; i++)
                #pragma unroll
                for (int j = 0; j < 8; j++) acc[i][j] += a[i] * b[j];
        }
        __syncthreads();
    }

    #pragma unroll
    for (int i = 0; i < 8; i++) {
        int row = m0 + ty * 8 + i;
        int t = g_perm[row];
        if (t < 0) continue;                    // pad row: never scattered
        float sc = g_score[t];
        float* orow = out + (size_t)t * CC + n0 + tx * 8;
        #pragma unroll
        for (int j = 0; j < 8; j++)
            acc[i][j] = (acc[i][j] + b2[(size_t)e * CC + n0 + tx * 8 + j]) * sc;
        *(float4*)(orow)     = *(float4*)(&acc[i][0]);
        *(float4*)(orow + 4) = *(float4*)(&acc[i][4]);
    }
}

// ---------------- launch ----------------------------------------------------
extern "C" void kernel_launch(void* const* d_in, const int* in_sizes, int n_in,
                              void* d_out, int out_size) {
    const float* x      = (const float*)d_in[0];  // [1,2048,1024]
    const float* wg_red = (const float*)d_in[1];  // [16,1024]
    const float* wg     = (const float*)d_in[2];  // [8,16]
    const float* w1     = (const float*)d_in[3];  // [8,1024,4096]
    const float* b1     = (const float*)d_in[4];  // [8,4096]
    const float* w2     = (const float*)d_in[5];  // [8,4096,1024]
    const float* b2     = (const float*)d_in[6];  // [8,1024]
    float* out = (float*)d_out;                   // [1,2048,1024] fp32

    prep_kernel<<<1, 32>>>(wg);
    gate_kernel<<<TT / 8, 256>>>(x, wg_red);
    offs_kernel<<<1, 32>>>();
    initperm_kernel<<<RCAP / 256, 256>>>();
    scatter_kernel<<<TT / 256, 256>>>();
    gather_kernel<<<RCAP, 256>>>(x);
    gemm1_kernel<<<dim3(HH / 128, RCAP / 128), 256>>>(w1, b1);
    gemm2_kernel<<<dim3(CC / 128, RCAP / 128), 256>>>(w2, b2, out);
}

// round 3
// speedup vs baseline: 3.0593x; 3.0593x over previous
#include <cuda_runtime.h>
#include <math.h>
#include <cstdint>

// Problem constants
#define TT   2048
#define CC   1024
#define HH   4096
#define NE   8
#define NG   16
#define RCAP 3072
#define EPSN 1e-4f

// ---------------- device scratch ----------------
__device__ float g_unit[NE * NG];
__device__ int   g_idx[TT];
__device__ float g_score[TT];
__device__ int   g_counts[NE];
__device__ int   g_off[NE + 1];
__device__ int   g_fill[NE];
__device__ int   g_perm[RCAP];
__device__ float g_Xg[(size_t)RCAP * CC];
__device__ float g_H[(size_t)RCAP * HH];

// ---------------- PTX helpers (sm_100-safe: sm_80-era features only) -------
#define CP16(dst, src) asm volatile("cp.async.cg.shared.global [%0], [%1], 16;" :: "r"(dst), "l"(src))
#define CPCOMMIT()     asm volatile("cp.async.commit_group;" ::: "memory")
#define CPWAIT2()      asm volatile("cp.async.wait_group 2;" ::: "memory")

__device__ __forceinline__ uint32_t f2tf(float f) {
    uint32_t r;
    asm("cvt.rna.tf32.f32 %0, %1;" : "=r"(r) : "f"(f));
    return r;
}
__device__ __forceinline__ void mma_tf32(float* c, const uint32_t* a, const uint32_t* b) {
    asm volatile("mma.sync.aligned.m16n8k8.row.col.f32.tf32.tf32.f32 "
        "{%0,%1,%2,%3}, {%4,%5,%6,%7}, {%8,%9}, {%0,%1,%2,%3};"
        : "+f"(c[0]), "+f"(c[1]), "+f"(c[2]), "+f"(c[3])
        : "r"(a[0]), "r"(a[1]), "r"(a[2]), "r"(a[3]), "r"(b[0]), "r"(b[1]));
}

// ---------------- kernel 0: gate prep ----------------
__global__ void prep_kernel(const float* __restrict__ wg) {
    int tid = threadIdx.x;
    if (tid < NE) {
        float s = 0.f;
        #pragma unroll
        for (int g = 0; g < NG; g++) { float v = wg[tid * NG + g]; s += v * v; }
        float nrm = fmaxf(sqrtf(s), EPSN);
        #pragma unroll
        for (int g = 0; g < NG; g++) g_unit[tid * NG + g] = wg[tid * NG + g] / nrm;
        g_counts[tid] = 0;
        g_fill[tid]   = 0;
    }
}

// ---------------- kernel 1: gating ----------------
__global__ void gate_kernel(const float* __restrict__ x,
                            const float* __restrict__ wgred) {
    int warp = threadIdx.x >> 5;
    int lane = threadIdx.x & 31;
    int t = blockIdx.x * 8 + warp;
    const float* xr = x + (size_t)t * CC;

    float acc[NG];
    #pragma unroll
    for (int g = 0; g < NG; g++) acc[g] = 0.f;
    for (int c = lane; c < CC; c += 32) {
        float xv = xr[c];
        #pragma unroll
        for (int g = 0; g < NG; g++) acc[g] += xv * wgred[g * CC + c];
    }
    #pragma unroll
    for (int g = 0; g < NG; g++) {
        #pragma unroll
        for (int o = 16; o > 0; o >>= 1)
            acc[g] += __shfl_xor_sync(0xFFFFFFFFu, acc[g], o);
    }
    float logit = -1e30f;
    if (lane < NE) {
        float s = 0.f;
        #pragma unroll
        for (int g = 0; g < NG; g++) s += acc[g] * g_unit[lane * NG + g];
        logit = s;
    }
    float m = logit;
    #pragma unroll
    for (int o = 4; o > 0; o >>= 1) m = fmaxf(m, __shfl_xor_sync(0xFFFFFFFFu, m, o));
    int idxm = (lane < NE && logit == m) ? lane : NE;
    #pragma unroll
    for (int o = 4; o > 0; o >>= 1) idxm = min(idxm, __shfl_xor_sync(0xFFFFFFFFu, idxm, o));
    float ssum = (lane < NE) ? expf(logit - m) : 0.f;
    #pragma unroll
    for (int o = 4; o > 0; o >>= 1) ssum += __shfl_xor_sync(0xFFFFFFFFu, ssum, o);
    if (lane == 0) {
        g_idx[t]   = idxm;
        g_score[t] = 1.f / ssum;
        atomicAdd(&g_counts[idxm], 1);
    }
}

// ---------------- kernels 2-5 ----------------
__global__ void offs_kernel() {
    if (threadIdx.x == 0 && blockIdx.x == 0) {
        int o = 0;
        for (int e = 0; e < NE; e++) { g_off[e] = o; o += (g_counts[e] + 127) & ~127; }
        g_off[NE] = o;
    }
}
__global__ void initperm_kernel() {
    int i = blockIdx.x * blockDim.x + threadIdx.x;
    if (i < RCAP) g_perm[i] = -1;
}
__global__ void scatter_kernel() {
    int t = blockIdx.x * blockDim.x + threadIdx.x;
    if (t < TT) {
        int e = g_idx[t];
        int p = g_off[e] + atomicAdd(&g_fill[e], 1);
        g_perm[p] = t;
    }
}
__global__ void gather_kernel(const float* __restrict__ x) {
    int r = blockIdx.x;
    int t = g_perm[r];
    float4* dst = (float4*)(g_Xg + (size_t)r * CC);
    if (t >= 0) {
        const float4* src = (const float4*)(x + (size_t)t * CC);
        dst[threadIdx.x] = src[threadIdx.x];
    } else {
        dst[threadIdx.x] = make_float4(0.f, 0.f, 0.f, 0.f);
    }
}

// ---------------- tf32 mma.sync grouped GEMM ----------------
// CTA tile 128x128, BK=32, 3-stage cp.async pipeline, 8 warps (2x4), warp 64x32.
// MODE 0: H = gelu(Xg @ w1[e] + b1[e]);  A = g_Xg, KTOT=CC, LDB=HH
// MODE 1: out[tok] = (H @ w2[e] + b2[e]) * score;  A = g_H, KTOT=HH, LDB=CC
#define ASTR 36       // A smem row stride (floats): 32 + 4 pad
#define BSTR 136      // B smem row stride (floats): 128 + 8 pad
#define SF   (128 * ASTR + 32 * BSTR)   // floats per stage = 8960
#define SMEMSZ (3 * SF * 4)             // 107520 bytes

template<int KTOT, int LDB, int MODE>
__global__ __launch_bounds__(256, 2)
void gemm_mma(const float* __restrict__ Bw, const float* __restrict__ bias,
              float* __restrict__ outp) {
    constexpr int BK = 32;
    constexpr int NKC = KTOT / BK;

    extern __shared__ float smem[];
    int tid = threadIdx.x, lane = tid & 31, wid = tid >> 5;
    int wm0 = (wid & 1) * 64;       // warp m offset in CTA tile
    int wn0 = (wid >> 1) * 32;      // warp n offset

    int m0 = blockIdx.x * 128;      // m fastest: same-expert CTAs adjacent (L2 reuse of B)
    int n0 = blockIdx.y * 128;
    if (m0 >= g_off[NE]) return;
    int e = 0;
    #pragma unroll
    for (int i = 1; i < NE; i++) if (m0 >= g_off[i]) e = i;
    if (m0 >= g_off[e] + g_counts[e]) return;

    const float* Abase = (MODE == 0 ? g_Xg : g_H) + (size_t)m0 * KTOT;
    const float* Bbase = Bw + (size_t)e * KTOT * LDB + n0;

    uint32_t sbase = (uint32_t)__cvta_generic_to_shared(smem);

    // stage loader: 2048 x 16B chunks, 8 per thread
    auto load_stage = [&](int stg, int k0) {
        uint32_t sA = sbase + (uint32_t)(stg * SF) * 4u;
        uint32_t sB = sA + 128u * ASTR * 4u;
        #pragma unroll
        for (int it = 0; it < 4; it++) {            // A: 128 rows x 8 chunks
            int idx = it * 256 + tid;
            int m = idx >> 3, j = idx & 7;
            CP16(sA + (uint32_t)(m * ASTR + j * 4) * 4u,
                 Abase + (size_t)m * KTOT + k0 + j * 4);
        }
        #pragma unroll
        for (int it = 0; it < 4; it++) {            // B: 32 rows x 32 chunks
            int idx = it * 256 + tid;
            int k = idx >> 5, j = idx & 31;
            CP16(sB + (uint32_t)(k * BSTR + j * 4) * 4u,
                 Bbase + (size_t)(k0 + k) * LDB + j * 4);
        }
    };

    float acc[4][4][4];
    #pragma unroll
    for (int mi = 0; mi < 4; mi++)
        #pragma unroll
        for (int ni = 0; ni < 4; ni++)
            #pragma unroll
            for (int q = 0; q < 4; q++) acc[mi][ni][q] = 0.f;

    load_stage(0, 0); CPCOMMIT();
    load_stage(1, BK); CPCOMMIT();

    for (int i = 0; i < NKC; i++) {
        if (i + 2 < NKC) { load_stage((i + 2) % 3, (i + 2) * BK); }
        CPCOMMIT();                       // uniform group count (empty on tail)
        CPWAIT2();                        // <=2 pending -> stage i resident
        __syncthreads();

        const float* As = smem + (i % 3) * SF;          // [128][ASTR]
        const float* Bs = As + 128 * ASTR;              // [32][BSTR]
        #pragma unroll
        for (int ks = 0; ks < 4; ks++) {
            int kb = ks * 8;
            uint32_t af[4][4], bf[4][2];
            #pragma unroll
            for (int mi = 0; mi < 4; mi++) {
                int r = wm0 + mi * 16 + (lane >> 2);
                int c = kb + (lane & 3);
                af[mi][0] = f2tf(As[r * ASTR + c]);
                af[mi][1] = f2tf(As[(r + 8) * ASTR + c]);
                af[mi][2] = f2tf(As[r * ASTR + c + 4]);
                af[mi][3] = f2tf(As[(r + 8) * ASTR + c + 4]);
            }
            #pragma unroll
            for (int ni = 0; ni < 4; ni++) {
                int n = wn0 + ni * 8 + (lane >> 2);
                int kk = kb + (lane & 3);
                bf[ni][0] = f2tf(Bs[kk * BSTR + n]);
                bf[ni][1] = f2tf(Bs[(kk + 4) * BSTR + n]);
            }
            #pragma unroll
            for (int mi = 0; mi < 4; mi++)
                #pragma unroll
                for (int ni = 0; ni < 4; ni++)
                    mma_tf32(acc[mi][ni], af[mi], bf[ni]);
        }
        __syncthreads();                  // protect stage buffer before rewrite
    }

    // ---------------- epilogue ----------------
    #pragma unroll
    for (int mi = 0; mi < 4; mi++) {
        int r0 = m0 + wm0 + mi * 16 + (lane >> 2);      // rows r0, r0+8
        int tok0 = 0, tok1 = 0; float sc0 = 0.f, sc1 = 0.f;
        if (MODE == 1) {
            tok0 = g_perm[r0];     if (tok0 >= 0) sc0 = g_score[tok0];
            tok1 = g_perm[r0 + 8]; if (tok1 >= 0) sc1 = g_score[tok1];
        }
        #pragma unroll
        for (int ni = 0; ni < 4; ni++) {
            int c = n0 + wn0 + ni * 8 + ((lane & 3) << 1);
            float bsv0 = bias[(size_t)e * LDB + c];
            float bsv1 = bias[(size_t)e * LDB + c + 1];
            if (MODE == 0) {
                float v0 = acc[mi][ni][0] + bsv0;
                float v1 = acc[mi][ni][1] + bsv1;
                float v2 = acc[mi][ni][2] + bsv0;
                float v3 = acc[mi][ni][3] + bsv1;
                v0 = 0.5f * v0 * (1.0f + erff(v0 * 0.70710678118654752f));
                v1 = 0.5f * v1 * (1.0f + erff(v1 * 0.70710678118654752f));
                v2 = 0.5f * v2 * (1.0f + erff(v2 * 0.70710678118654752f));
                v3 = 0.5f * v3 * (1.0f + erff(v3 * 0.70710678118654752f));
                *(float2*)(g_H + (size_t)r0 * HH + c)       = make_float2(v0, v1);
                *(float2*)(g_H + (size_t)(r0 + 8) * HH + c) = make_float2(v2, v3);
            } else {
                if (tok0 >= 0) {
                    float v0 = (acc[mi][ni][0] + bsv0) * sc0;
                    float v1 = (acc[mi][ni][1] + bsv1) * sc0;
                    *(float2*)(outp + (size_t)tok0 * CC + c) = make_float2(v0, v1);
                }
                if (tok1 >= 0) {
                    float v2 = (acc[mi][ni][2] + bsv0) * sc1;
                    float v3 = (acc[mi][ni][3] + bsv1) * sc1;
                    *(float2*)(outp + (size_t)tok1 * CC + c) = make_float2(v2, v3);
                }
            }
        }
    }
}

// ---------------- launch ----------------
extern "C" void kernel_launch(void* const* d_in, const int* in_sizes, int n_in,
                              void* d_out, int out_size) {
    const float* x      = (const float*)d_in[0];
    const float* wg_red = (const float*)d_in[1];
    const float* wg     = (const float*)d_in[2];
    const float* w1     = (const float*)d_in[3];
    const float* b1     = (const float*)d_in[4];
    const float* w2     = (const float*)d_in[5];
    const float* b2     = (const float*)d_in[6];
    float* out = (float*)d_out;

    cudaFuncSetAttribute(gemm_mma<CC, HH, 0>, cudaFuncAttributeMaxDynamicSharedMemorySize, SMEMSZ);
    cudaFuncSetAttribute(gemm_mma<HH, CC, 1>, cudaFuncAttributeMaxDynamicSharedMemorySize, SMEMSZ);

    prep_kernel<<<1, 32>>>(wg);
    gate_kernel<<<TT / 8, 256>>>(x, wg_red);
    offs_kernel<<<1, 32>>>();
    initperm_kernel<<<RCAP / 256, 256>>>();
    scatter_kernel<<<TT / 256, 256>>>();
    gather_kernel<<<RCAP, 256>>>(x);
    gemm_mma<CC, HH, 0><<<dim3(RCAP / 128, HH / 128), 256, SMEMSZ>>>(w1, b1, nullptr);
    gemm_mma<HH, CC, 1><<<dim3(RCAP / 128, CC / 128), 256, SMEMSZ>>>(w2, b2, out);
}

// round 4
// speedup vs baseline: 3.3155x; 1.0838x over previous
#include <cuda_runtime.h>
#include <math.h>
#include <cstdint>

// Problem constants
#define TT   2048
#define CC   1024
#define HH   4096
#define NE   8
#define NG   16
#define RCAP 3072
#define EPSN 1e-4f

// ---------------- device scratch ----------------
__device__ float g_unit[NE * NG];
__device__ int   g_idx[TT];
__device__ float g_score[TT];
__device__ int   g_counts[NE];
__device__ int   g_off[NE + 1];
__device__ int   g_fill[NE];
__device__ int   g_perm[RCAP];
__device__ float g_Xg[(size_t)RCAP * CC];   // stored pre-rounded to tf32
__device__ float g_H[(size_t)RCAP * HH];    // stored pre-rounded to tf32

// ---------------- PTX helpers (sm_100-safe) ----------------
#define CP16(dst, src) asm volatile("cp.async.cg.shared.global [%0], [%1], 16;" :: "r"(dst), "l"(src))
#define CPCOMMIT()     asm volatile("cp.async.commit_group;" ::: "memory")
#define CPWAIT2()      asm volatile("cp.async.wait_group 2;" ::: "memory")

__device__ __forceinline__ float f2tf_f(float f) {   // RNA round to tf32, as float
    uint32_t r;
    asm("cvt.rna.tf32.f32 %0, %1;" : "=r"(r) : "f"(f));
    return __uint_as_float(r);
}
__device__ __forceinline__ void mma_tf32(float* c, const uint32_t* a, const uint32_t* b) {
    asm volatile("mma.sync.aligned.m16n8k8.row.col.f32.tf32.tf32.f32 "
        "{%0,%1,%2,%3}, {%4,%5,%6,%7}, {%8,%9}, {%0,%1,%2,%3};"
        : "+f"(c[0]), "+f"(c[1]), "+f"(c[2]), "+f"(c[3])
        : "r"(a[0]), "r"(a[1]), "r"(a[2]), "r"(a[3]), "r"(b[0]), "r"(b[1]));
}

// ---------------- kernel 0: gate prep ----------------
__global__ void prep_kernel(const float* __restrict__ wg) {
    int tid = threadIdx.x;
    if (tid < NE) {
        float s = 0.f;
        #pragma unroll
        for (int g = 0; g < NG; g++) { float v = wg[tid * NG + g]; s += v * v; }
        float nrm = fmaxf(sqrtf(s), EPSN);
        #pragma unroll
        for (int g = 0; g < NG; g++) g_unit[tid * NG + g] = wg[tid * NG + g] / nrm;
        g_counts[tid] = 0;
        g_fill[tid]   = 0;
    }
}

// ---------------- kernel 1: gating ----------------
__global__ void gate_kernel(const float* __restrict__ x,
                            const float* __restrict__ wgred) {
    int warp = threadIdx.x >> 5;
    int lane = threadIdx.x & 31;
    int t = blockIdx.x * 8 + warp;
    const float* xr = x + (size_t)t * CC;

    float acc[NG];
    #pragma unroll
    for (int g = 0; g < NG; g++) acc[g] = 0.f;
    for (int c = lane; c < CC; c += 32) {
        float xv = xr[c];
        #pragma unroll
        for (int g = 0; g < NG; g++) acc[g] += xv * wgred[g * CC + c];
    }
    #pragma unroll
    for (int g = 0; g < NG; g++) {
        #pragma unroll
        for (int o = 16; o > 0; o >>= 1)
            acc[g] += __shfl_xor_sync(0xFFFFFFFFu, acc[g], o);
    }
    float logit = -1e30f;
    if (lane < NE) {
        float s = 0.f;
        #pragma unroll
        for (int g = 0; g < NG; g++) s += acc[g] * g_unit[lane * NG + g];
        logit = s;
    }
    float m = logit;
    #pragma unroll
    for (int o = 4; o > 0; o >>= 1) m = fmaxf(m, __shfl_xor_sync(0xFFFFFFFFu, m, o));
    int idxm = (lane < NE && logit == m) ? lane : NE;
    #pragma unroll
    for (int o = 4; o > 0; o >>= 1) idxm = min(idxm, __shfl_xor_sync(0xFFFFFFFFu, idxm, o));
    float ssum = (lane < NE) ? expf(logit - m) : 0.f;
    #pragma unroll
    for (int o = 4; o > 0; o >>= 1) ssum += __shfl_xor_sync(0xFFFFFFFFu, ssum, o);
    if (lane == 0) {
        g_idx[t]   = idxm;
        g_score[t] = 1.f / ssum;
        atomicAdd(&g_counts[idxm], 1);
    }
}

// ---------------- kernels 2-5 ----------------
__global__ void offs_kernel() {
    if (threadIdx.x == 0 && blockIdx.x == 0) {
        int o = 0;
        for (int e = 0; e < NE; e++) { g_off[e] = o; o += (g_counts[e] + 127) & ~127; }
        g_off[NE] = o;
    }
}
__global__ void initperm_kernel() {
    int i = blockIdx.x * blockDim.x + threadIdx.x;
    if (i < RCAP) g_perm[i] = -1;
}
__global__ void scatter_kernel() {
    int t = blockIdx.x * blockDim.x + threadIdx.x;
    if (t < TT) {
        int e = g_idx[t];
        int p = g_off[e] + atomicAdd(&g_fill[e], 1);
        g_perm[p] = t;
    }
}
__global__ void gather_kernel(const float* __restrict__ x) {
    int r = blockIdx.x;
    int t = g_perm[r];
    float4* dst = (float4*)(g_Xg + (size_t)r * CC);
    if (t >= 0) {
        const float4* src = (const float4*)(x + (size_t)t * CC);
        float4 v = src[threadIdx.x];
        v.x = f2tf_f(v.x); v.y = f2tf_f(v.y);      // pre-round to tf32 (RNA)
        v.z = f2tf_f(v.z); v.w = f2tf_f(v.w);
        dst[threadIdx.x] = v;
    } else {
        dst[threadIdx.x] = make_float4(0.f, 0.f, 0.f, 0.f);
    }
}

// ---------------- tf32 mma.sync grouped GEMM ----------------
// CTA 128x128, 4 warps (2x2 grid of 64x64 warp tiles), BK=32, 3-stage cp.async.
// Inner loop: raw-bit tf32 operands (A pre-rounded RNA at producer; B = HW RZ).
#define ASTR 36
#define BSTR 136
#define SF   (128 * ASTR + 32 * BSTR)   // 8960 floats / stage
#define SMEMSZ (3 * SF * 4)             // 107520 bytes

template<int KTOT, int LDB, int MODE>
__global__ __launch_bounds__(128, 2)
void gemm_mma(const float* __restrict__ Bw, const float* __restrict__ bias,
              float* __restrict__ outp) {
    constexpr int BK = 32;
    constexpr int NKC = KTOT / BK;

    extern __shared__ float smem[];
    int tid = threadIdx.x, lane = tid & 31, wid = tid >> 5;
    int wm0 = (wid & 1) * 64;
    int wn0 = (wid >> 1) * 64;

    int m0 = blockIdx.x * 128;      // m fastest: same-expert CTAs adjacent
    int n0 = blockIdx.y * 128;
    if (m0 >= g_off[NE]) return;
    int e = 0;
    #pragma unroll
    for (int i = 1; i < NE; i++) if (m0 >= g_off[i]) e = i;
    if (m0 >= g_off[e] + g_counts[e]) return;

    const float* Abase = (MODE == 0 ? g_Xg : g_H) + (size_t)m0 * KTOT;
    const float* Bbase = Bw + (size_t)e * KTOT * LDB + n0;

    uint32_t sbase = (uint32_t)__cvta_generic_to_shared(smem);

    // stage loader: 2048 x 16B chunks, 16 per thread (128 threads)
    auto load_stage = [&](int stg, int k0) {
        uint32_t sA = sbase + (uint32_t)(stg * SF) * 4u;
        uint32_t sB = sA + 128u * ASTR * 4u;
        #pragma unroll
        for (int it = 0; it < 8; it++) {            // A: 128 rows x 8 chunks
            int idx = it * 128 + tid;
            int m = idx >> 3, j = idx & 7;
            CP16(sA + (uint32_t)(m * ASTR + j * 4) * 4u,
                 Abase + (size_t)m * KTOT + k0 + j * 4);
        }
        #pragma unroll
        for (int it = 0; it < 8; it++) {            // B: 32 rows x 32 chunks
            int idx = it * 128 + tid;
            int k = idx >> 5, j = idx & 31;
            CP16(sB + (uint32_t)(k * BSTR + j * 4) * 4u,
                 Bbase + (size_t)(k0 + k) * LDB + j * 4);
        }
    };

    float acc[4][8][4];
    #pragma unroll
    for (int mi = 0; mi < 4; mi++)
        #pragma unroll
        for (int ni = 0; ni < 8; ni++)
            #pragma unroll
            for (int q = 0; q < 4; q++) acc[mi][ni][q] = 0.f;

    load_stage(0, 0); CPCOMMIT();
    load_stage(1, BK); CPCOMMIT();

    for (int i = 0; i < NKC; i++) {
        if (i + 2 < NKC) { load_stage((i + 2) % 3, (i + 2) * BK); }
        CPCOMMIT();
        CPWAIT2();
        __syncthreads();

        const uint32_t* As = (const uint32_t*)(smem + (i % 3) * SF);
        const uint32_t* Bs = As + 128 * ASTR;
        #pragma unroll
        for (int ks = 0; ks < 4; ks++) {
            int kb = ks * 8;
            uint32_t af[4][4], bf[8][2];
            #pragma unroll
            for (int mi = 0; mi < 4; mi++) {
                int r = wm0 + mi * 16 + (lane >> 2);
                int c = kb + (lane & 3);
                af[mi][0] = As[r * ASTR + c];
                af[mi][1] = As[(r + 8) * ASTR + c];
                af[mi][2] = As[r * ASTR + c + 4];
                af[mi][3] = As[(r + 8) * ASTR + c + 4];
            }
            #pragma unroll
            for (int ni = 0; ni < 8; ni++) {
                int n = wn0 + ni * 8 + (lane >> 2);
                int kk = kb + (lane & 3);
                bf[ni][0] = Bs[kk * BSTR + n];
                bf[ni][1] = Bs[(kk + 4) * BSTR + n];
            }
            #pragma unroll
            for (int mi = 0; mi < 4; mi++)
                #pragma unroll
                for (int ni = 0; ni < 8; ni++)
                    mma_tf32(acc[mi][ni], af[mi], bf[ni]);
        }
        __syncthreads();
    }

    // ---------------- epilogue ----------------
    #pragma unroll
    for (int mi = 0; mi < 4; mi++) {
        int r0 = m0 + wm0 + mi * 16 + (lane >> 2);
        int tok0 = 0, tok1 = 0; float sc0 = 0.f, sc1 = 0.f;
        if (MODE == 1) {
            tok0 = g_perm[r0];     if (tok0 >= 0) sc0 = g_score[tok0];
            tok1 = g_perm[r0 + 8]; if (tok1 >= 0) sc1 = g_score[tok1];
        }
        #pragma unroll
        for (int ni = 0; ni < 8; ni++) {
            int c = n0 + wn0 + ni * 8 + ((lane & 3) << 1);
            float bsv0 = bias[(size_t)e * LDB + c];
            float bsv1 = bias[(size_t)e * LDB + c + 1];
            if (MODE == 0) {
                float v0 = acc[mi][ni][0] + bsv0;
                float v1 = acc[mi][ni][1] + bsv1;
                float v2 = acc[mi][ni][2] + bsv0;
                float v3 = acc[mi][ni][3] + bsv1;
                v0 = 0.5f * v0 * (1.0f + erff(v0 * 0.70710678118654752f));
                v1 = 0.5f * v1 * (1.0f + erff(v1 * 0.70710678118654752f));
                v2 = 0.5f * v2 * (1.0f + erff(v2 * 0.70710678118654752f));
                v3 = 0.5f * v3 * (1.0f + erff(v3 * 0.70710678118654752f));
                // store pre-rounded tf32 so GEMM2 can feed raw bits
                *(float2*)(g_H + (size_t)r0 * HH + c)       = make_float2(f2tf_f(v0), f2tf_f(v1));
                *(float2*)(g_H + (size_t)(r0 + 8) * HH + c) = make_float2(f2tf_f(v2), f2tf_f(v3));
            } else {
                if (tok0 >= 0) {
                    float v0 = (acc[mi][ni][0] + bsv0) * sc0;
                    float v1 = (acc[mi][ni][1] + bsv1) * sc0;
                    *(float2*)(outp + (size_t)tok0 * CC + c) = make_float2(v0, v1);
                }
                if (tok1 >= 0) {
                    float v2 = (acc[mi][ni][2] + bsv0) * sc1;
                    float v3 = (acc[mi][ni][3] + bsv1) * sc1;
                    *(float2*)(outp + (size_t)tok1 * CC + c) = make_float2(v2, v3);
                }
            }
        }
    }
}

// ---------------- launch ----------------
extern "C" void kernel_launch(void* const* d_in, const int* in_sizes, int n_in,
                              void* d_out, int out_size) {
    const float* x      = (const float*)d_in[0];
    const float* wg_red = (const float*)d_in[1];
    const float* wg     = (const float*)d_in[2];
    const float* w1     = (const float*)d_in[3];
    const float* b1     = (const float*)d_in[4];
    const float* w2     = (const float*)d_in[5];
    const float* b2     = (const float*)d_in[6];
    float* out = (float*)d_out;

    cudaFuncSetAttribute(gemm_mma<CC, HH, 0>, cudaFuncAttributeMaxDynamicSharedMemorySize, SMEMSZ);
    cudaFuncSetAttribute(gemm_mma<HH, CC, 1>, cudaFuncAttributeMaxDynamicSharedMemorySize, SMEMSZ);

    prep_kernel<<<1, 32>>>(wg);
    gate_kernel<<<TT / 8, 256>>>(x, wg_red);
    offs_kernel<<<1, 32>>>();
    initperm_kernel<<<RCAP / 256, 256>>>();
    scatter_kernel<<<TT / 256, 256>>>();
    gather_kernel<<<RCAP, 256>>>(x);
    gemm_mma<CC, HH, 0><<<dim3(RCAP / 128, HH / 128), 128, SMEMSZ>>>(w1, b1, nullptr);
    gemm_mma<HH, CC, 1><<<dim3(RCAP / 128, CC / 128), 128, SMEMSZ>>>(w2, b2, out);
}

// round 6
// speedup vs baseline: 3.5921x; 1.0834x over previous
#include <cuda_runtime.h>
#include <math.h>
#include <cstdint>

// Problem constants
#define TT   2048
#define CC   1024
#define HH   4096
#define NE   8
#define NG   16
#define RCAP 3072
#define EPSN 1e-4f

// ---------------- device scratch ----------------
__device__ float g_unit[NE * NG];
__device__ int   g_idx[TT];
__device__ float g_score[TT];
__device__ int   g_counts[NE];
__device__ int   g_off[NE + 1];
__device__ int   g_fill[NE];
__device__ int   g_perm[RCAP];
// A operands stored FRAGMENT-PERMUTED for m16n8k8 tf32 mma:
// float index (m,k) -> ((m>>4)*(K/8) + (k>>3))*128 + (((m&7)<<2)|(k&3))*4 + ((m>>3)&1) + (((k>>2)&1)<<1)
__device__ float g_Xg[(size_t)RCAP * CC];   // pre-rounded tf32, permuted
__device__ float g_H[(size_t)RCAP * HH];    // pre-rounded tf32, permuted

// ---------------- PTX helpers ----------------
#define CP16(dst, src) asm volatile("cp.async.cg.shared.global [%0], [%1], 16;" :: "r"(dst), "l"(src))
#define CPCOMMIT()     asm volatile("cp.async.commit_group;" ::: "memory")
#define CPWAIT2()      asm volatile("cp.async.wait_group 2;" ::: "memory")

__device__ __forceinline__ float f2tf_f(float f) {
    uint32_t r;
    asm("cvt.rna.tf32.f32 %0, %1;" : "=r"(r) : "f"(f));
    return __uint_as_float(r);
}
__device__ __forceinline__ void mma_tf32(float* c, const uint32_t* a, const uint32_t* b) {
    asm volatile("mma.sync.aligned.m16n8k8.row.col.f32.tf32.tf32.f32 "
        "{%0,%1,%2,%3}, {%4,%5,%6,%7}, {%8,%9}, {%0,%1,%2,%3};"
        : "+f"(c[0]), "+f"(c[1]), "+f"(c[2]), "+f"(c[3])
        : "r"(a[0]), "r"(a[1]), "r"(a[2]), "r"(a[3]), "r"(b[0]), "r"(b[1]));
}
// permuted float-offset for A layouts (K8 = K/8)
__device__ __forceinline__ size_t perm_off(int m, int k, int K8) {
    return (size_t)((m >> 4) * K8 + (k >> 3)) * 128
         + ((((m & 7) << 2) | (k & 3)) << 2) + ((m >> 3) & 1) + (((k >> 2) & 1) << 1);
}

// ---------------- kernel 0: gate prep ----------------
__global__ void prep_kernel(const float* __restrict__ wg) {
    int tid = threadIdx.x;
    if (tid < NE) {
        float s = 0.f;
        #pragma unroll
        for (int g = 0; g < NG; g++) { float v = wg[tid * NG + g]; s += v * v; }
        float nrm = fmaxf(sqrtf(s), EPSN);
        #pragma unroll
        for (int g = 0; g < NG; g++) g_unit[tid * NG + g] = wg[tid * NG + g] / nrm;
        g_counts[tid] = 0;
        g_fill[tid]   = 0;
    }
}

// ---------------- kernel 1: gating ----------------
__global__ void gate_kernel(const float* __restrict__ x,
                            const float* __restrict__ wgred) {
    int warp = threadIdx.x >> 5;
    int lane = threadIdx.x & 31;
    int t = blockIdx.x * 8 + warp;
    const float* xr = x + (size_t)t * CC;

    float acc[NG];
    #pragma unroll
    for (int g = 0; g < NG; g++) acc[g] = 0.f;
    for (int c = lane; c < CC; c += 32) {
        float xv = xr[c];
        #pragma unroll
        for (int g = 0; g < NG; g++) acc[g] += xv * wgred[g * CC + c];
    }
    #pragma unroll
    for (int g = 0; g < NG; g++) {
        #pragma unroll
        for (int o = 16; o > 0; o >>= 1)
            acc[g] += __shfl_xor_sync(0xFFFFFFFFu, acc[g], o);
    }
    float logit = -1e30f;
    if (lane < NE) {
        float s = 0.f;
        #pragma unroll
        for (int g = 0; g < NG; g++) s += acc[g] * g_unit[lane * NG + g];
        logit = s;
    }
    float m = logit;
    #pragma unroll
    for (int o = 4; o > 0; o >>= 1) m = fmaxf(m, __shfl_xor_sync(0xFFFFFFFFu, m, o));
    int idxm = (lane < NE && logit == m) ? lane : NE;
    #pragma unroll
    for (int o = 4; o > 0; o >>= 1) idxm = min(idxm, __shfl_xor_sync(0xFFFFFFFFu, idxm, o));
    float ssum = (lane < NE) ? expf(logit - m) : 0.f;
    #pragma unroll
    for (int o = 4; o > 0; o >>= 1) ssum += __shfl_xor_sync(0xFFFFFFFFu, ssum, o);
    if (lane == 0) {
        g_idx[t]   = idxm;
        g_score[t] = 1.f / ssum;
        atomicAdd(&g_counts[idxm], 1);
    }
}

// ---------------- kernels 2-4 ----------------
__global__ void offs_kernel() {
    if (threadIdx.x == 0 && blockIdx.x == 0) {
        int o = 0;
        for (int e = 0; e < NE; e++) { g_off[e] = o; o += (g_counts[e] + 127) & ~127; }
        g_off[NE] = o;
    }
}
__global__ void scatter_kernel() {
    int t = blockIdx.x * blockDim.x + threadIdx.x;
    if (t < TT) {
        int e = g_idx[t];
        int p = g_off[e] + atomicAdd(&g_fill[e], 1);
        g_perm[p] = t;
    }
}
// gather x rows -> g_Xg (permuted + tf32-rounded); pad rows zeroed
__global__ void gather_kernel(const float* __restrict__ x) {
    int r = blockIdx.x;
    int e = 0;
    #pragma unroll
    for (int i = 1; i < NE; i++) if (r >= g_off[i]) e = i;
    bool valid = (r - g_off[e]) < g_counts[e];
    int k = threadIdx.x * 4;
    float4 v = make_float4(0.f, 0.f, 0.f, 0.f);
    if (valid) {
        int t = g_perm[r];
        v = *(const float4*)(x + (size_t)t * CC + k);
        v.x = f2tf_f(v.x); v.y = f2tf_f(v.y);
        v.z = f2tf_f(v.z); v.w = f2tf_f(v.w);
    }
    g_Xg[perm_off(r, k + 0, CC / 8)] = v.x;
    g_Xg[perm_off(r, k + 1, CC / 8)] = v.y;
    g_Xg[perm_off(r, k + 2, CC / 8)] = v.z;
    g_Xg[perm_off(r, k + 3, CC / 8)] = v.w;
}

// ---------------- tf32 mma.sync grouped GEMM ----------------
// 4 warps, warp tile (BM/2) x 64, CTA tile BM x 128, BK=32, 3-stage cp.async.
// A smem: fragment-permuted blocks of 512B; B smem: [32][132] k-major.
// A operand resolved INSIDE device code via MODE (device globals!).
#define BSTR 132

template<int BM, int KTOT, int LDB, int MODE, int MAXB>
__global__ __launch_bounds__(128, MAXB)
void gemm_mma(const float* __restrict__ Bw, const float* __restrict__ bias,
              float* __restrict__ outp) {
    constexpr int BK = 32;
    constexpr int NKC = KTOT / BK;
    constexpr int K8  = KTOT / 8;
    constexpr int MI  = BM / 32;               // m fragments per warp
    constexpr int AF = BM * BK;                // A floats per stage
    constexpr int SFf = AF + 32 * BSTR;        // floats per stage

    extern __shared__ float smem[];
    int tid = threadIdx.x, lane = tid & 31, wid = tid >> 5;
    int wm0 = (wid & 1) * (BM / 2);
    int wn0 = (wid >> 1) * 64;

    int m0 = blockIdx.x * BM;                  // m fastest: same-expert CTAs adjacent
    int n0 = blockIdx.y * 128;
    if (m0 >= g_off[NE]) return;
    int e = 0;
    #pragma unroll
    for (int i = 1; i < NE; i++) if (m0 >= g_off[i]) e = i;
    if (m0 >= g_off[e] + g_counts[e]) return;

    const float* Aperm = (MODE == 0) ? g_Xg : g_H;       // device-side resolve
    const float* Abase = Aperm + (size_t)(m0 >> 4) * K8 * 128;
    const float* Bbase = Bw + (size_t)e * KTOT * LDB + n0;

    uint32_t sbase = (uint32_t)__cvta_generic_to_shared(smem);

    auto load_stage = [&](int stg, int k0) {
        uint32_t sA = sbase + (uint32_t)(stg * SFf) * 4u;
        uint32_t sB = sA + (uint32_t)AF * 4u;
        constexpr int ACH = AF / 4;            // 16B chunks in A stage
        #pragma unroll
        for (int it = 0; it < ACH / 128; it++) {
            int cidx = it * 128 + tid;
            int blk = cidx >> 5, c16 = cidx & 31;
            int i = blk >> 2, j = blk & 3;
            CP16(sA + (uint32_t)(blk * 128 + c16 * 4) * 4u,
                 Abase + ((size_t)i * K8 + (k0 >> 3) + j) * 128 + c16 * 4);
        }
        #pragma unroll
        for (int it = 0; it < 8; it++) {
            int idx = it * 128 + tid;
            int k = idx >> 5, j = idx & 31;
            CP16(sB + (uint32_t)(k * BSTR + j * 4) * 4u,
                 Bbase + (size_t)(k0 + k) * LDB + j * 4);
        }
    };

    float acc[MI][8][4];
    #pragma unroll
    for (int mi = 0; mi < MI; mi++)
        #pragma unroll
        for (int ni = 0; ni < 8; ni++)
            #pragma unroll
            for (int q = 0; q < 4; q++) acc[mi][ni][q] = 0.f;

    load_stage(0, 0); CPCOMMIT();
    load_stage(1, BK); CPCOMMIT();

    uint32_t af[2][MI][4], bf[2][8][2];

    for (int i = 0; i < NKC; i++) {
        if (i + 2 < NKC) { load_stage((i + 2) % 3, (i + 2) * BK); }
        CPCOMMIT();
        CPWAIT2();
        __syncthreads();

        const uint4* Ab = (const uint4*)(smem + (i % 3) * SFf);
        const uint32_t* Bs = (const uint32_t*)(smem + (i % 3) * SFf + AF);

        auto ldfrag = [&](int buf, int ks) {
            #pragma unroll
            for (int mi = 0; mi < MI; mi++) {
                uint4 v = Ab[(((wm0 >> 4) + mi) * 4 + ks) * 32 + lane];
                af[buf][mi][0] = v.x; af[buf][mi][1] = v.y;
                af[buf][mi][2] = v.z; af[buf][mi][3] = v.w;
            }
            int kk = ks * 8 + (lane & 3);
            int nb = wn0 + (lane >> 2);
            #pragma unroll
            for (int ni = 0; ni < 8; ni++) {
                bf[buf][ni][0] = Bs[kk * BSTR + nb + ni * 8];
                bf[buf][ni][1] = Bs[(kk + 4) * BSTR + nb + ni * 8];
            }
        };

        ldfrag(0, 0);
        #pragma unroll
        for (int ks = 0; ks < 4; ks++) {
            int cur = ks & 1;
            if (ks < 3) ldfrag(cur ^ 1, ks + 1);
            #pragma unroll
            for (int mi = 0; mi < MI; mi++)
                #pragma unroll
                for (int ni = 0; ni < 8; ni++)
                    mma_tf32(acc[mi][ni], af[cur][mi], bf[cur][ni]);
        }
        __syncthreads();
    }

    // ---------------- epilogue ----------------
    #pragma unroll
    for (int mi = 0; mi < MI; mi++) {
        int r0 = m0 + wm0 + mi * 16 + (lane >> 2);
        int tok0 = -1, tok1 = -1; float sc0 = 0.f, sc1 = 0.f;
        if (MODE == 1) {
            if ((r0 - g_off[e]) < g_counts[e])     { tok0 = g_perm[r0];     sc0 = g_score[tok0]; }
            if ((r0 + 8 - g_off[e]) < g_counts[e]) { tok1 = g_perm[r0 + 8]; sc1 = g_score[tok1]; }
        }
        #pragma unroll
        for (int ni = 0; ni < 8; ni++) {
            int c = n0 + wn0 + ni * 8 + ((lane & 3) << 1);
            float bsv0 = bias[(size_t)e * LDB + c];
            float bsv1 = bias[(size_t)e * LDB + c + 1];
            if (MODE == 0) {
                float v0 = acc[mi][ni][0] + bsv0;
                float v1 = acc[mi][ni][1] + bsv1;
                float v2 = acc[mi][ni][2] + bsv0;
                float v3 = acc[mi][ni][3] + bsv1;
                v0 = 0.5f * v0 * (1.0f + erff(v0 * 0.70710678118654752f));
                v1 = 0.5f * v1 * (1.0f + erff(v1 * 0.70710678118654752f));
                v2 = 0.5f * v2 * (1.0f + erff(v2 * 0.70710678118654752f));
                v3 = 0.5f * v3 * (1.0f + erff(v3 * 0.70710678118654752f));
                g_H[perm_off(r0,     c,     HH / 8)] = f2tf_f(v0);
                g_H[perm_off(r0,     c + 1, HH / 8)] = f2tf_f(v1);
                g_H[perm_off(r0 + 8, c,     HH / 8)] = f2tf_f(v2);
                g_H[perm_off(r0 + 8, c + 1, HH / 8)] = f2tf_f(v3);
            } else {
                if (tok0 >= 0) {
                    float v0 = (acc[mi][ni][0] + bsv0) * sc0;
                    float v1 = (acc[mi][ni][1] + bsv1) * sc0;
                    *(float2*)(outp + (size_t)tok0 * CC + c) = make_float2(v0, v1);
                }
                if (tok1 >= 0) {
                    float v2 = (acc[mi][ni][2] + bsv0) * sc1;
                    float v3 = (acc[mi][ni][3] + bsv1) * sc1;
                    *(float2*)(outp + (size_t)tok1 * CC + c) = make_float2(v2, v3);
                }
            }
        }
    }
}

// smem sizes
#define SM1 (3 * (128 * 32 + 32 * BSTR) * 4)   // 99840
#define SM2 (3 * (64 * 32 + 32 * BSTR) * 4)    // 75264

// ---------------- launch ----------------
extern "C" void kernel_launch(void* const* d_in, const int* in_sizes, int n_in,
                              void* d_out, int out_size) {
    const float* x      = (const float*)d_in[0];
    const float* wg_red = (const float*)d_in[1];
    const float* wg     = (const float*)d_in[2];
    const float* w1     = (const float*)d_in[3];
    const float* b1     = (const float*)d_in[4];
    const float* w2     = (const float*)d_in[5];
    const float* b2     = (const float*)d_in[6];
    float* out = (float*)d_out;

    cudaFuncSetAttribute(gemm_mma<128, CC, HH, 0, 2>,
                         cudaFuncAttributeMaxDynamicSharedMemorySize, SM1);
    cudaFuncSetAttribute(gemm_mma<64, HH, CC, 1, 3>,
                         cudaFuncAttributeMaxDynamicSharedMemorySize, SM2);

    prep_kernel<<<1, 32>>>(wg);
    gate_kernel<<<TT / 8, 256>>>(x, wg_red);
    offs_kernel<<<1, 32>>>();
    scatter_kernel<<<TT / 256, 256>>>();
    gather_kernel<<<RCAP, 256>>>(x);
    // launch index 5 -> ncu -s 5 profiles gemm1
    gemm_mma<128, CC, HH, 0, 2><<<dim3(RCAP / 128, HH / 128), 128, SM1>>>(w1, b1, nullptr);
    gemm_mma<64, HH, CC, 1, 3><<<dim3(RCAP / 64, CC / 128), 128, SM2>>>(w2, b2, out);
}

// round 8
// speedup vs baseline: 4.0912x; 1.1390x over previous
#include <cuda_runtime.h>
#include <cuda_fp16.h>
#include <math.h>
#include <cstdint>

// Problem constants
#define TT   2048
#define CC   1024
#define HH   4096
#define NE   8
#define NG   16
#define RCAP 3072
#define EPSN 1e-4f

// ---------------- device scratch ----------------
__device__ int    g_idx[TT];
__device__ float  g_score[TT];
__device__ int    g_counts[NE];
__device__ int    g_off[NE + 1];
__device__ int    g_perm[RCAP];
__device__ __half g_Xg[(size_t)RCAP * CC];   // row-major half (RN-rounded x)
__device__ __half g_H[(size_t)RCAP * HH];    // row-major half (GEMM1 output)

// ---------------- PTX helpers ----------------
#define CP16(dst, src) asm volatile("cp.async.cg.shared.global [%0], [%1], 16;" :: "r"(dst), "l"(src))
#define CPCOMMIT()     asm volatile("cp.async.commit_group;" ::: "memory")
#define CPWAIT1()      asm volatile("cp.async.wait_group 1;" ::: "memory")

__device__ __forceinline__ void ldsm_x4(uint32_t a, uint32_t& r0, uint32_t& r1,
                                        uint32_t& r2, uint32_t& r3) {
    asm volatile("ldmatrix.sync.aligned.m8n8.x4.shared.b16 {%0,%1,%2,%3}, [%4];"
        : "=r"(r0), "=r"(r1), "=r"(r2), "=r"(r3) : "r"(a));
}
__device__ __forceinline__ void ldsm_x2t(uint32_t a, uint32_t& r0, uint32_t& r1) {
    asm volatile("ldmatrix.sync.aligned.m8n8.x2.trans.shared.b16 {%0,%1}, [%2];"
        : "=r"(r0), "=r"(r1) : "r"(a));
}
__device__ __forceinline__ void mma_f16(float* c, const uint32_t* a, const uint32_t* b) {
    asm volatile("mma.sync.aligned.m16n8k16.row.col.f32.f16.f16.f32 "
        "{%0,%1,%2,%3}, {%4,%5,%6,%7}, {%8,%9}, {%0,%1,%2,%3};"
        : "+f"(c[0]), "+f"(c[1]), "+f"(c[2]), "+f"(c[3])
        : "r"(a[0]), "r"(a[1]), "r"(a[2]), "r"(a[3]), "r"(b[0]), "r"(b[1]));
}
#define STS64(addr, u0, u1) \
    asm volatile("st.shared.v2.b32 [%0], {%1,%2};" :: "r"(addr), "r"(u0), "r"(u1))

// ---------------- kernel 0: gating (unit-norm fused per block) ----------------
__global__ void gate_kernel(const float* __restrict__ x,
                            const float* __restrict__ wgred,
                            const float* __restrict__ wg) {
    __shared__ float s_unit[NE * NG];
    int warp = threadIdx.x >> 5;
    int lane = threadIdx.x & 31;
    if (threadIdx.x < NE) {
        float s = 0.f;
        #pragma unroll
        for (int g = 0; g < NG; g++) { float v = wg[threadIdx.x * NG + g]; s += v * v; }
        float nrm = fmaxf(sqrtf(s), EPSN);
        #pragma unroll
        for (int g = 0; g < NG; g++) s_unit[threadIdx.x * NG + g] = wg[threadIdx.x * NG + g] / nrm;
    }
    __syncthreads();

    int t = blockIdx.x * 8 + warp;
    const float* xr = x + (size_t)t * CC;
    float acc[NG];
    #pragma unroll
    for (int g = 0; g < NG; g++) acc[g] = 0.f;
    for (int c = lane; c < CC; c += 32) {
        float xv = xr[c];
        #pragma unroll
        for (int g = 0; g < NG; g++) acc[g] += xv * wgred[g * CC + c];
    }
    #pragma unroll
    for (int g = 0; g < NG; g++) {
        #pragma unroll
        for (int o = 16; o > 0; o >>= 1)
            acc[g] += __shfl_xor_sync(0xFFFFFFFFu, acc[g], o);
    }
    float logit = -1e30f;
    if (lane < NE) {
        float s = 0.f;
        #pragma unroll
        for (int g = 0; g < NG; g++) s += acc[g] * s_unit[lane * NG + g];
        logit = s;
    }
    float m = logit;
    #pragma unroll
    for (int o = 4; o > 0; o >>= 1) m = fmaxf(m, __shfl_xor_sync(0xFFFFFFFFu, m, o));
    int idxm = (lane < NE && logit == m) ? lane : NE;
    #pragma unroll
    for (int o = 4; o > 0; o >>= 1) idxm = min(idxm, __shfl_xor_sync(0xFFFFFFFFu, idxm, o));
    float ssum = (lane < NE) ? expf(logit - m) : 0.f;
    #pragma unroll
    for (int o = 4; o > 0; o >>= 1) ssum += __shfl_xor_sync(0xFFFFFFFFu, ssum, o);
    if (lane == 0) {
        g_idx[t]   = idxm;
        g_score[t] = 1.f / ssum;
    }
}

// ---------------- kernel 1: offsets + scatter (single block) ----------------
__global__ void offs_scatter_kernel() {
    __shared__ int hist[NE], sfill[NE], soff[NE];
    int tid = threadIdx.x;
    if (tid < NE) { hist[tid] = 0; sfill[tid] = 0; }
    __syncthreads();
    for (int t = tid; t < TT; t += 256) atomicAdd(&hist[g_idx[t]], 1);
    __syncthreads();
    if (tid == 0) {
        int o = 0;
        for (int e = 0; e < NE; e++) {
            g_off[e] = o; soff[e] = o;
            g_counts[e] = hist[e];
            o += (hist[e] + 127) & ~127;
        }
        g_off[NE] = o;
    }
    __syncthreads();
    for (int t = tid; t < TT; t += 256) {
        int e = g_idx[t];
        int p = soff[e] + atomicAdd(&sfill[e], 1);
        g_perm[p] = t;
    }
}

// ---------------- kernel 2: gather x -> half rows ----------------
__global__ void gather_kernel(const float* __restrict__ x) {
    int r = blockIdx.x;
    int e = 0;
    #pragma unroll
    for (int i = 1; i < NE; i++) if (r >= g_off[i]) e = i;
    bool valid = (r - g_off[e]) < g_counts[e];
    int k = threadIdx.x * 4;
    __half2 h0 = __floats2half2_rn(0.f, 0.f), h1 = h0;
    if (valid) {
        int t = g_perm[r];
        float4 v = *(const float4*)(x + (size_t)t * CC + k);
        h0 = __floats2half2_rn(v.x, v.y);
        h1 = __floats2half2_rn(v.z, v.w);
    }
    uint2 pk = make_uint2(*(uint32_t*)&h0, *(uint32_t*)&h1);
    *(uint2*)(g_Xg + (size_t)r * CC + k) = pk;
}

// ---------------- fp16 mma grouped GEMM ----------------
// CTA tile BM x 128, BK=32, 3-stage ring. 4 warps: warp tile (BM/2) x 64.
// A: half rows via cp.async, frag via ldmatrix.x4 (row stride 80B, conflict-free).
// B: fp32 LDG 2 stages ahead -> cvt -> STS.64 half (row stride 272B), ldmatrix.x2.trans.
#define ASTRH 40      // A smem row stride in halves (32+8)
#define BSTRH 136     // B smem row stride in halves (128+8)

template<int BM, int KTOT, int LDB, int MODE, int MAXB>
__global__ __launch_bounds__(128, MAXB)
void gemm_mma(const float* __restrict__ Bw, const float* __restrict__ bias,
              float* __restrict__ outp) {
    constexpr int BK = 32;
    constexpr int NKC = KTOT / BK;
    constexpr int MI  = BM / 32;                       // 16-row m-frags per warp
    constexpr int SFh = BM * ASTRH + 32 * BSTRH;       // halves per stage
    constexpr int NB  = (MODE == 0) ? 8 : 4;           // B staging regs (float4s)

    extern __shared__ __half smem[];
    int tid = threadIdx.x, lane = tid & 31, wid = tid >> 5;
    int wm0 = (wid & 1) * (BM / 2);
    int wn0 = (wid >> 1) * 64;

    int m0 = blockIdx.x * BM;
    int n0 = blockIdx.y * 128;
    if (m0 >= g_off[NE]) return;
    int e = 0;
    #pragma unroll
    for (int i = 1; i < NE; i++) if (m0 >= g_off[i]) e = i;
    if (m0 >= g_off[e] + g_counts[e]) return;

    const __half* Abase = ((MODE == 0) ? g_Xg : g_H) + (size_t)m0 * KTOT;
    const float*  Bbase = Bw + (size_t)e * KTOT * LDB + n0;

    uint32_t sbase = (uint32_t)__cvta_generic_to_shared(smem);

    // A loader: BM rows x 32 halves (64B) per stage
    auto cpA = [&](int stg, int k0) {
        uint32_t sA = sbase + (uint32_t)(stg * SFh) * 2u;
        #pragma unroll
        for (int it = 0; it < BM / 32; it++) {         // BM*4 chunks /128 thr
            int idx = it * 128 + tid;
            int r = idx >> 2, j = idx & 3;
            CP16(sA + (uint32_t)(r * ASTRH + j * 8) * 2u,
                 Abase + (size_t)r * KTOT + k0 + j * 8);
        }
    };
    // B staging: NB x LDG.128 per thread per half-batch (32 k x 128 n fp32 total)
    float4 fB[NB];
    auto ldgB = [&](int k0, int half) {
        #pragma unroll
        for (int it = 0; it < NB; it++) {
            int idx = (half * NB + it) * 128 + tid;
            int k = idx >> 5, c = idx & 31;
            fB[it] = *(const float4*)(Bbase + (size_t)(k0 + k) * LDB + c * 4);
        }
    };
    auto stsB = [&](int stg, int half) {
        uint32_t sB = sbase + (uint32_t)(stg * SFh + BM * ASTRH) * 2u;
        #pragma unroll
        for (int it = 0; it < NB; it++) {
            int idx = (half * NB + it) * 128 + tid;
            int k = idx >> 5, c = idx & 31;
            __half2 h0 = __floats2half2_rn(fB[it].x, fB[it].y);
            __half2 h1 = __floats2half2_rn(fB[it].z, fB[it].w);
            STS64(sB + (uint32_t)(k * BSTRH + c * 4) * 2u,
                  *(uint32_t*)&h0, *(uint32_t*)&h1);
        }
    };
    // stage B fully (1 or 2 half-batches depending on NB)
    auto stageB = [&](int stg, int k0) {
        if (MODE == 0) { ldgB(k0, 0); stsB(stg, 0); }
        else { ldgB(k0, 0); stsB(stg, 0); ldgB(k0, 1); stsB(stg, 1); }
    };

    float acc[MI][8][4];
    #pragma unroll
    for (int mi = 0; mi < MI; mi++)
        #pragma unroll
        for (int ni = 0; ni < 8; ni++)
            #pragma unroll
            for (int q = 0; q < 4; q++) acc[mi][ni][q] = 0.f;

    // prologue: A stages 0,1 in flight; B stage 0 resident
    cpA(0, 0); CPCOMMIT();
    cpA(1, BK); CPCOMMIT();
    stageB(0, 0);

    for (int i = 0; i < NKC; i++) {
        CPWAIT1();                       // A(i) resident
        __syncthreads();                 // A(i)+B(i) visible; ring slots drained
        if (i + 1 < NKC) stageB((i + 1) % 3, (i + 1) * BK);
        if (i + 2 < NKC) cpA((i + 2) % 3, (i + 2) * BK);
        CPCOMMIT();

        uint32_t sA = sbase + (uint32_t)((i % 3) * SFh) * 2u;
        uint32_t sB = sbase + (uint32_t)((i % 3) * SFh + BM * ASTRH) * 2u;
        #pragma unroll
        for (int ks = 0; ks < 2; ks++) {
            uint32_t af[MI][4], bf[8][2];
            #pragma unroll
            for (int mi = 0; mi < MI; mi++) {
                uint32_t a = sA + (uint32_t)((wm0 + mi * 16 + (lane & 15)) * ASTRH) * 2u
                           + (uint32_t)(ks * 32 + (lane >> 4) * 16);
                ldsm_x4(a, af[mi][0], af[mi][1], af[mi][2], af[mi][3]);
            }
            #pragma unroll
            for (int ni = 0; ni < 8; ni++) {
                uint32_t b = sB + (uint32_t)((ks * 16 + (lane & 15)) * BSTRH) * 2u
                           + (uint32_t)((wn0 + ni * 8) * 2);
                ldsm_x2t(b, bf[ni][0], bf[ni][1]);
            }
            #pragma unroll
            for (int mi = 0; mi < MI; mi++)
                #pragma unroll
                for (int ni = 0; ni < 8; ni++)
                    mma_f16(acc[mi][ni], af[mi], bf[ni]);
        }
    }

    // ---------------- epilogue ----------------
    #pragma unroll
    for (int mi = 0; mi < MI; mi++) {
        int r0 = m0 + wm0 + mi * 16 + (lane >> 2);
        int tok0 = -1, tok1 = -1; float sc0 = 0.f, sc1 = 0.f;
        if (MODE == 1) {
            if ((r0 - g_off[e]) < g_counts[e])     { tok0 = g_perm[r0];     sc0 = g_score[tok0]; }
            if ((r0 + 8 - g_off[e]) < g_counts[e]) { tok1 = g_perm[r0 + 8]; sc1 = g_score[tok1]; }
        }
        #pragma unroll
        for (int ni = 0; ni < 8; ni++) {
            int c = n0 + wn0 + ni * 8 + ((lane & 3) << 1);
            float bsv0 = bias[(size_t)e * LDB + c];
            float bsv1 = bias[(size_t)e * LDB + c + 1];
            if (MODE == 0) {
                float v0 = acc[mi][ni][0] + bsv0;
                float v1 = acc[mi][ni][1] + bsv1;
                float v2 = acc[mi][ni][2] + bsv0;
                float v3 = acc[mi][ni][3] + bsv1;
                v0 = 0.5f * v0 * (1.0f + erff(v0 * 0.70710678118654752f));
                v1 = 0.5f * v1 * (1.0f + erff(v1 * 0.70710678118654752f));
                v2 = 0.5f * v2 * (1.0f + erff(v2 * 0.70710678118654752f));
                v3 = 0.5f * v3 * (1.0f + erff(v3 * 0.70710678118654752f));
                __half2 h01 = __floats2half2_rn(v0, v1);
                __half2 h23 = __floats2half2_rn(v2, v3);
                *(uint32_t*)(g_H + (size_t)r0 * HH + c)       = *(uint32_t*)&h01;
                *(uint32_t*)(g_H + (size_t)(r0 + 8) * HH + c) = *(uint32_t*)&h23;
            } else {
                if (tok0 >= 0) {
                    float v0 = (acc[mi][ni][0] + bsv0) * sc0;
                    float v1 = (acc[mi][ni][1] + bsv1) * sc0;
                    *(float2*)(outp + (size_t)tok0 * CC + c) = make_float2(v0, v1);
                }
                if (tok1 >= 0) {
                    float v2 = (acc[mi][ni][2] + bsv0) * sc1;
                    float v3 = (acc[mi][ni][3] + bsv1) * sc1;
                    *(float2*)(outp + (size_t)tok1 * CC + c) = make_float2(v2, v3);
                }
            }
        }
    }
}

// smem bytes
#define SM1 (3 * (128 * ASTRH + 32 * BSTRH) * 2)   // 56832
#define SM2 (3 * (64 * ASTRH + 32 * BSTRH) * 2)    // 41472

// ---------------- launch ----------------
extern "C" void kernel_launch(void* const* d_in, const int* in_sizes, int n_in,
                              void* d_out, int out_size) {
    const float* x      = (const float*)d_in[0];
    const float* wg_red = (const float*)d_in[1];
    const float* wg     = (const float*)d_in[2];
    const float* w1     = (const float*)d_in[3];
    const float* b1     = (const float*)d_in[4];
    const float* w2     = (const float*)d_in[5];
    const float* b2     = (const float*)d_in[6];
    float* out = (float*)d_out;

    cudaFuncSetAttribute(gemm_mma<128, CC, HH, 0, 2>,
                         cudaFuncAttributeMaxDynamicSharedMemorySize, SM1);
    cudaFuncSetAttribute(gemm_mma<64, HH, CC, 1, 3>,
                         cudaFuncAttributeMaxDynamicSharedMemorySize, SM2);

    gate_kernel<<<TT / 8, 256>>>(x, wg_red, wg);          // launch 0
    offs_scatter_kernel<<<1, 256>>>();                    // launch 1
    gather_kernel<<<RCAP, 256>>>(x);                      // launch 2
    gemm_mma<128, CC, HH, 0, 2>                           // launch 3 <- ncu lands here
        <<<dim3(RCAP / 128, HH / 128), 128, SM1>>>(w1, b1, nullptr);
    gemm_mma<64, HH, CC, 1, 3>                            // launch 4
        <<<dim3(RCAP / 64, CC / 128), 128, SM2>>>(w2, b2, out);
}

// round 9
// speedup vs baseline: 5.3147x; 1.2990x over previous
#include <cuda_runtime.h>
#include <cuda_fp16.h>
#include <math.h>
#include <cstdint>

// Problem constants
#define TT   2048
#define CC   1024
#define HH   4096
#define NE   8
#define NG   16
#define RCAP 3072
#define EPSN 1e-4f

// ---------------- device scratch ----------------
__device__ int    g_idx[TT];
__device__ float  g_score[TT];
__device__ int    g_counts[NE];
__device__ int    g_off[NE + 1];
__device__ int    g_perm[RCAP];
__device__ __half g_Xg[(size_t)RCAP * CC];   // row-major half (RN-rounded x)
__device__ __half g_H[(size_t)RCAP * HH];    // row-major half (GEMM1 output)

// ---------------- PTX helpers ----------------
#define CP16(dst, src) asm volatile("cp.async.cg.shared.global [%0], [%1], 16;" :: "r"(dst), "l"(src))
#define CPCOMMIT()     asm volatile("cp.async.commit_group;" ::: "memory")
#define CPWAIT1()      asm volatile("cp.async.wait_group 1;" ::: "memory")

__device__ __forceinline__ void ldsm_x4(uint32_t a, uint32_t& r0, uint32_t& r1,
                                        uint32_t& r2, uint32_t& r3) {
    asm volatile("ldmatrix.sync.aligned.m8n8.x4.shared.b16 {%0,%1,%2,%3}, [%4];"
        : "=r"(r0), "=r"(r1), "=r"(r2), "=r"(r3) : "r"(a));
}
__device__ __forceinline__ void ldsm_x2t(uint32_t a, uint32_t& r0, uint32_t& r1) {
    asm volatile("ldmatrix.sync.aligned.m8n8.x2.trans.shared.b16 {%0,%1}, [%2];"
        : "=r"(r0), "=r"(r1) : "r"(a));
}
__device__ __forceinline__ void mma_f16(float* c, const uint32_t* a, const uint32_t* b) {
    asm volatile("mma.sync.aligned.m16n8k16.row.col.f32.f16.f16.f32 "
        "{%0,%1,%2,%3}, {%4,%5,%6,%7}, {%8,%9}, {%0,%1,%2,%3};"
        : "+f"(c[0]), "+f"(c[1]), "+f"(c[2]), "+f"(c[3])
        : "r"(a[0]), "r"(a[1]), "r"(a[2]), "r"(a[3]), "r"(b[0]), "r"(b[1]));
}
#define STS64(addr, u0, u1) \
    asm volatile("st.shared.v2.b32 [%0], {%1,%2};" :: "r"(addr), "r"(u0), "r"(u1))

// ---------------- kernel 0: gating ----------------
__global__ void gate_kernel(const float* __restrict__ x,
                            const float* __restrict__ wgred,
                            const float* __restrict__ wg) {
    __shared__ float s_unit[NE * NG];
    int warp = threadIdx.x >> 5;
    int lane = threadIdx.x & 31;
    if (threadIdx.x < NE) {
        float s = 0.f;
        #pragma unroll
        for (int g = 0; g < NG; g++) { float v = wg[threadIdx.x * NG + g]; s += v * v; }
        float nrm = fmaxf(sqrtf(s), EPSN);
        #pragma unroll
        for (int g = 0; g < NG; g++) s_unit[threadIdx.x * NG + g] = wg[threadIdx.x * NG + g] / nrm;
    }
    __syncthreads();

    int t = blockIdx.x * 8 + warp;
    const float* xr = x + (size_t)t * CC;
    float acc[NG];
    #pragma unroll
    for (int g = 0; g < NG; g++) acc[g] = 0.f;
    for (int c = lane; c < CC; c += 32) {
        float xv = xr[c];
        #pragma unroll
        for (int g = 0; g < NG; g++) acc[g] += xv * wgred[g * CC + c];
    }
    #pragma unroll
    for (int g = 0; g < NG; g++) {
        #pragma unroll
        for (int o = 16; o > 0; o >>= 1)
            acc[g] += __shfl_xor_sync(0xFFFFFFFFu, acc[g], o);
    }
    float logit = -1e30f;
    if (lane < NE) {
        float s = 0.f;
        #pragma unroll
        for (int g = 0; g < NG; g++) s += acc[g] * s_unit[lane * NG + g];
        logit = s;
    }
    float m = logit;
    #pragma unroll
    for (int o = 4; o > 0; o >>= 1) m = fmaxf(m, __shfl_xor_sync(0xFFFFFFFFu, m, o));
    int idxm = (lane < NE && logit == m) ? lane : NE;
    #pragma unroll
    for (int o = 4; o > 0; o >>= 1) idxm = min(idxm, __shfl_xor_sync(0xFFFFFFFFu, idxm, o));
    float ssum = (lane < NE) ? expf(logit - m) : 0.f;
    #pragma unroll
    for (int o = 4; o > 0; o >>= 1) ssum += __shfl_xor_sync(0xFFFFFFFFu, ssum, o);
    if (lane == 0) {
        g_idx[t]   = idxm;
        g_score[t] = 1.f / ssum;
    }
}

// ---------------- kernel 1: offsets + scatter (single block) ----------------
__global__ void offs_scatter_kernel() {
    __shared__ int hist[NE], sfill[NE], soff[NE];
    int tid = threadIdx.x;
    if (tid < NE) { hist[tid] = 0; sfill[tid] = 0; }
    __syncthreads();
    for (int t = tid; t < TT; t += 256) atomicAdd(&hist[g_idx[t]], 1);
    __syncthreads();
    if (tid == 0) {
        int o = 0;
        for (int e = 0; e < NE; e++) {
            g_off[e] = o; soff[e] = o;
            g_counts[e] = hist[e];
            o += (hist[e] + 127) & ~127;
        }
        g_off[NE] = o;
    }
    __syncthreads();
    for (int t = tid; t < TT; t += 256) {
        int e = g_idx[t];
        int p = soff[e] + atomicAdd(&sfill[e], 1);
        g_perm[p] = t;
    }
}

// ---------------- kernel 2: gather x -> half rows ----------------
__global__ void gather_kernel(const float* __restrict__ x) {
    int r = blockIdx.x;
    int e = 0;
    #pragma unroll
    for (int i = 1; i < NE; i++) if (r >= g_off[i]) e = i;
    bool valid = (r - g_off[e]) < g_counts[e];
    int k = threadIdx.x * 4;
    __half2 h0 = __floats2half2_rn(0.f, 0.f), h1 = h0;
    if (valid) {
        int t = g_perm[r];
        float4 v = *(const float4*)(x + (size_t)t * CC + k);
        h0 = __floats2half2_rn(v.x, v.y);
        h1 = __floats2half2_rn(v.z, v.w);
    }
    uint2 pk = make_uint2(*(uint32_t*)&h0, *(uint32_t*)&h1);
    *(uint2*)(g_Xg + (size_t)r * CC + k) = pk;
}

// ---------------- fp16 mma grouped GEMM ----------------
// CTA tile BM x 128, BK=32, 3-stage ring, 4 warps: warp tile (BM/2) x 64.
// Pipelined B: fB regs carry stage i+1 across iteration i (LDG under MMA phase).
#define ASTRH 40      // A smem row stride in halves (32+8)
#define BSTRH 136     // B smem row stride in halves (128+8)

template<int BM, int KTOT, int LDB, int MODE, int MAXB>
__global__ __launch_bounds__(128, MAXB)
void gemm_mma(const float* __restrict__ Bw, const float* __restrict__ bias,
              float* __restrict__ outp) {
    constexpr int BK = 32;
    constexpr int NKC = KTOT / BK;
    constexpr int MI  = BM / 32;                       // 16-row m-frags per warp
    constexpr int SFh = BM * ASTRH + 32 * BSTRH;       // halves per stage

    extern __shared__ __half smem[];
    int tid = threadIdx.x, lane = tid & 31, wid = tid >> 5;
    int wm0 = (wid & 1) * (BM / 2);
    int wn0 = (wid >> 1) * 64;

    int m0 = blockIdx.x * BM;
    int n0 = blockIdx.y * 128;
    if (m0 >= g_off[NE]) return;
    int e = 0;
    #pragma unroll
    for (int i = 1; i < NE; i++) if (m0 >= g_off[i]) e = i;
    if (m0 >= g_off[e] + g_counts[e]) return;

    const __half* Abase = ((MODE == 0) ? g_Xg : g_H) + (size_t)m0 * KTOT;
    const float*  Bbase = Bw + (size_t)e * KTOT * LDB + n0;

    uint32_t sbase = (uint32_t)__cvta_generic_to_shared(smem);

    // A loader: BM rows x 32 halves (64B) per stage
    auto cpA = [&](int stg, int k0) {
        uint32_t sA = sbase + (uint32_t)(stg * SFh) * 2u;
        #pragma unroll
        for (int it = 0; it < BM / 32; it++) {
            int idx = it * 128 + tid;
            int r = idx >> 2, j = idx & 3;
            CP16(sA + (uint32_t)(r * ASTRH + j * 8) * 2u,
                 Abase + (size_t)r * KTOT + k0 + j * 8);
        }
    };
    // B pipeline: 8 x LDG.128 per thread held in regs across one iteration
    float4 fB[8];
    auto ldgB = [&](int k0) {
        #pragma unroll
        for (int it = 0; it < 8; it++) {
            int idx = it * 128 + tid;
            int k = idx >> 5, c = idx & 31;
            fB[it] = *(const float4*)(Bbase + (size_t)(k0 + k) * LDB + c * 4);
        }
    };
    auto stsB = [&](int stg) {
        uint32_t sB = sbase + (uint32_t)(stg * SFh + BM * ASTRH) * 2u;
        #pragma unroll
        for (int it = 0; it < 8; it++) {
            int idx = it * 128 + tid;
            int k = idx >> 5, c = idx & 31;
            __half2 h0 = __floats2half2_rn(fB[it].x, fB[it].y);
            __half2 h1 = __floats2half2_rn(fB[it].z, fB[it].w);
            STS64(sB + (uint32_t)(k * BSTRH + c * 4) * 2u,
                  *(uint32_t*)&h0, *(uint32_t*)&h1);
        }
    };

    float acc[MI][8][4];
    #pragma unroll
    for (int mi = 0; mi < MI; mi++)
        #pragma unroll
        for (int ni = 0; ni < 8; ni++)
            #pragma unroll
            for (int q = 0; q < 4; q++) acc[mi][ni][q] = 0.f;

    // hoisted ldmatrix lane offsets (bytes)
    uint32_t aoff[MI], boff;
    #pragma unroll
    for (int mi = 0; mi < MI; mi++)
        aoff[mi] = (uint32_t)((wm0 + mi * 16 + (lane & 15)) * ASTRH) * 2u
                 + (uint32_t)((lane >> 4) * 16);
    boff = (uint32_t)((lane & 15) * BSTRH) * 2u + (uint32_t)(wn0 * 2);

    // prologue: B(0) in smem; fB holds B(1); A(0),A(1) in flight
    ldgB(0);
    cpA(0, 0); CPCOMMIT();
    stsB(0);
    ldgB(BK);
    cpA(1, BK); CPCOMMIT();

    for (int i = 0; i < NKC; i++) {
        CPWAIT1();                       // A(i) resident
        __syncthreads();                 // A(i)+B(i) visible; ring slots drained
        if (i + 1 < NKC) stsB((i + 1) % 3);          // from fB (no stall)
        if (i + 2 < NKC) {
            ldgB((i + 2) * BK);          // latency hidden under MMA phase
            cpA((i + 2) % 3, (i + 2) * BK);
        }
        CPCOMMIT();

        uint32_t sA = sbase + (uint32_t)((i % 3) * SFh) * 2u;
        uint32_t sB = sbase + (uint32_t)((i % 3) * SFh + BM * ASTRH) * 2u;
        #pragma unroll
        for (int ks = 0; ks < 2; ks++) {
            uint32_t af[MI][4], bf[8][2];
            #pragma unroll
            for (int mi = 0; mi < MI; mi++)
                ldsm_x4(sA + aoff[mi] + (uint32_t)(ks * 32),
                        af[mi][0], af[mi][1], af[mi][2], af[mi][3]);
            #pragma unroll
            for (int ni = 0; ni < 8; ni++)
                ldsm_x2t(sB + boff + (uint32_t)(ks * 16 * BSTRH * 2 + ni * 16),
                         bf[ni][0], bf[ni][1]);
            #pragma unroll
            for (int mi = 0; mi < MI; mi++)
                #pragma unroll
                for (int ni = 0; ni < 8; ni++)
                    mma_f16(acc[mi][ni], af[mi], bf[ni]);
        }
    }

    // ---------------- epilogue ----------------
    #pragma unroll
    for (int mi = 0; mi < MI; mi++) {
        int r0 = m0 + wm0 + mi * 16 + (lane >> 2);
        int tok0 = -1, tok1 = -1; float sc0 = 0.f, sc1 = 0.f;
        if (MODE == 1) {
            if ((r0 - g_off[e]) < g_counts[e])     { tok0 = g_perm[r0];     sc0 = g_score[tok0]; }
            if ((r0 + 8 - g_off[e]) < g_counts[e]) { tok1 = g_perm[r0 + 8]; sc1 = g_score[tok1]; }
        }
        #pragma unroll
        for (int ni = 0; ni < 8; ni++) {
            int c = n0 + wn0 + ni * 8 + ((lane & 3) << 1);
            float bsv0 = bias[(size_t)e * LDB + c];
            float bsv1 = bias[(size_t)e * LDB + c + 1];
            if (MODE == 0) {
                float v0 = acc[mi][ni][0] + bsv0;
                float v1 = acc[mi][ni][1] + bsv1;
                float v2 = acc[mi][ni][2] + bsv0;
                float v3 = acc[mi][ni][3] + bsv1;
                v0 = 0.5f * v0 * (1.0f + erff(v0 * 0.70710678118654752f));
                v1 = 0.5f * v1 * (1.0f + erff(v1 * 0.70710678118654752f));
                v2 = 0.5f * v2 * (1.0f + erff(v2 * 0.70710678118654752f));
                v3 = 0.5f * v3 * (1.0f + erff(v3 * 0.70710678118654752f));
                __half2 h01 = __floats2half2_rn(v0, v1);
                __half2 h23 = __floats2half2_rn(v2, v3);
                *(uint32_t*)(g_H + (size_t)r0 * HH + c)       = *(uint32_t*)&h01;
                *(uint32_t*)(g_H + (size_t)(r0 + 8) * HH + c) = *(uint32_t*)&h23;
            } else {
                if (tok0 >= 0) {
                    float v0 = (acc[mi][ni][0] + bsv0) * sc0;
                    float v1 = (acc[mi][ni][1] + bsv1) * sc0;
                    *(float2*)(outp + (size_t)tok0 * CC + c) = make_float2(v0, v1);
                }
                if (tok1 >= 0) {
                    float v2 = (acc[mi][ni][2] + bsv0) * sc1;
                    float v3 = (acc[mi][ni][3] + bsv1) * sc1;
                    *(float2*)(outp + (size_t)tok1 * CC + c) = make_float2(v2, v3);
                }
            }
        }
    }
}

// smem bytes
#define SM1 (3 * (128 * ASTRH + 32 * BSTRH) * 2)   // 56832
#define SM2 (3 * (64 * ASTRH + 32 * BSTRH) * 2)    // 41472

// ---------------- launch ----------------
extern "C" void kernel_launch(void* const* d_in, const int* in_sizes, int n_in,
                              void* d_out, int out_size) {
    const float* x      = (const float*)d_in[0];
    const float* wg_red = (const float*)d_in[1];
    const float* wg     = (const float*)d_in[2];
    const float* w1     = (const float*)d_in[3];
    const float* b1     = (const float*)d_in[4];
    const float* w2     = (const float*)d_in[5];
    const float* b2     = (const float*)d_in[6];
    float* out = (float*)d_out;

    cudaFuncSetAttribute(gemm_mma<128, CC, HH, 0, 2>,
                         cudaFuncAttributeMaxDynamicSharedMemorySize, SM1);
    cudaFuncSetAttribute(gemm_mma<64, HH, CC, 1, 3>,
                         cudaFuncAttributeMaxDynamicSharedMemorySize, SM2);

    gate_kernel<<<TT / 8, 256>>>(x, wg_red, wg);          // launch 0
    offs_scatter_kernel<<<1, 256>>>();                    // launch 1
    gather_kernel<<<RCAP, 256>>>(x);                      // launch 2
    gemm_mma<128, CC, HH, 0, 2>                           // launch 3 <- ncu lands here
        <<<dim3(RCAP / 128, HH / 128), 128, SM1>>>(w1, b1, nullptr);
    gemm_mma<64, HH, CC, 1, 3>                            // launch 4
        <<<dim3(RCAP / 64, CC / 128), 128, SM2>>>(w2, b2, out);
}